// round 16
// baseline (speedup 1.0000x reference)
#include <cuda_runtime.h>
#include <cuda_fp16.h>
#include <cstdint>
#include <math.h>

// ---------------- problem constants ----------------
#define NUM_E 8
#define M_TOK 2048
#define H_DIM 1024
#define I_DIM 4096

// ---------------- fp16 scratch (no allocs allowed) ----------------
__device__ __half g_xh [(size_t)NUM_E * M_TOK * H_DIM];   //  32 MB
__device__ __half g_wih[(size_t)NUM_E * H_DIM * I_DIM];   //  64 MB
__device__ __half g_woh[(size_t)NUM_E * I_DIM * H_DIM];   //  64 MB
__device__ __half g_act[(size_t)NUM_E * M_TOK * I_DIM];   // 128 MB

// ---------------- tile config (round-13 proven shape) ----------------
#define BM 128
#define BN 128
#define BK 64
#define STAGES 3
#define ASTR 72             // halves; 144B rows -> ldsm rows hit banks 4r mod 32 (disjoint per phase)
#define BSTR 136            // halves; 272B rows -> banks 4k mod 32 (disjoint per phase)
#define A_HALVES (BM * ASTR)                 // 9216
#define B_HALVES (BK * BSTR)                 // 8704
#define STAGE_HALVES (A_HALVES + B_HALVES)   // 17920 halves = 35840 B
#define SMEM_BYTES (STAGES * STAGE_HALVES * 2)  // 107520 B/CTA -> 2 CTAs/SM

__device__ __forceinline__ void cp_async16(uint32_t smem, const void* gmem) {
    asm volatile("cp.async.cg.shared.global [%0], [%1], 16;\n" :: "r"(smem), "l"(gmem));
}
__device__ __forceinline__ void cp_commit() { asm volatile("cp.async.commit_group;\n" ::: "memory"); }
template <int N> __device__ __forceinline__ void cp_wait() {
    asm volatile("cp.async.wait_group %0;\n" :: "n"(N) : "memory");
}
__device__ __forceinline__ void ldsm_x4(uint32_t& r0, uint32_t& r1, uint32_t& r2, uint32_t& r3,
                                        uint32_t addr) {
    asm volatile("ldmatrix.sync.aligned.m8n8.x4.shared.b16 {%0,%1,%2,%3}, [%4];"
                 : "=r"(r0), "=r"(r1), "=r"(r2), "=r"(r3) : "r"(addr));
}
__device__ __forceinline__ void ldsm_x4_t(uint32_t& r0, uint32_t& r1, uint32_t& r2, uint32_t& r3,
                                          uint32_t addr) {
    asm volatile("ldmatrix.sync.aligned.m8n8.x4.trans.shared.b16 {%0,%1,%2,%3}, [%4];"
                 : "=r"(r0), "=r"(r1), "=r"(r2), "=r"(r3) : "r"(addr));
}
__device__ __forceinline__ float gelu_exact(float v) {
    return 0.5f * v * (1.0f + erff(v * 0.70710678118654752440f));
}

// ---------------- fp32 -> fp16 conversion (standalone) ----------------
__global__ void __launch_bounds__(256) cvt_f32_f16(const float* __restrict__ in,
                                                   __half* __restrict__ out, size_t n4) {
    size_t i = (size_t)blockIdx.x * blockDim.x + threadIdx.x;
    size_t stride = (size_t)gridDim.x * blockDim.x;
    const float4* in4 = (const float4*)in;
    uint2* out4 = (uint2*)out;
    for (; i < n4; i += stride) {
        float4 v = in4[i];
        __half2 lo = __float22half2_rn(make_float2(v.x, v.y));
        __half2 hi = __float22half2_rn(make_float2(v.z, v.w));
        uint2 o; o.x = *(uint32_t*)&lo; o.y = *(uint32_t*)&hi;
        out4[i] = o;
    }
}

// ---------------- fp16 GEMM: 256 threads, 8 warps (2x4), warp tile 64x32 ----------------
// A: [Mdim, Kdim] fp16 row-major per expert.  B: [Kdim, Ndim] fp16 row-major per expert.
// GELU=true: D fp16 + optional tail convert. GELU=false: D fp32.
// ACC16=true: per-MMA fp16 accumulate (C=0) promoted to fp32 each step (2x rate probe).
template <bool GELU, bool ACC16>
__global__ void __launch_bounds__(256, 2) gemm_f16_w8(
    const __half* __restrict__ Aall, const __half* __restrict__ Ball, void* __restrict__ Dall,
    int Mdim, int Ndim, int Kdim,
    const float* __restrict__ cvt_src, __half* __restrict__ cvt_dst, size_t cvt_n4)
{
    extern __shared__ __half smem[];
    const uint32_t smem_base = (uint32_t)__cvta_generic_to_shared(smem);

    const int e = blockIdx.z;
    const __half* A = Aall + (size_t)e * Mdim * Kdim + (size_t)blockIdx.y * BM * Kdim;
    const __half* B = Ball + (size_t)e * Kdim * Ndim + (size_t)blockIdx.x * BN;

    const int tid = threadIdx.x;
    const int warp = tid >> 5;
    const int lane = tid & 31;
    const int wm = warp >> 2;      // 0..1 -> 64-row band
    const int wn = warp & 3;       // 0..3 -> 32-col band
    const int grp = lane >> 2;     // 0..7
    const int qid = lane & 3;      // 0..3
    const int lrow = lane & 15;
    const int lcol8 = (lane >> 4) * 8;

    const int KT = Kdim / BK;

    auto issue_loads = [&](int chunk) {
        uint32_t s = smem_base + (uint32_t)(chunk % STAGES) * (STAGE_HALVES * 2);
        const __half* Ac = A + chunk * BK;
        const __half* Bc = B + (size_t)chunk * BK * Ndim;
        // A tile: 128 rows x 8 chunks of 16B = 1024 -> 4 per thread
        #pragma unroll
        for (int i = 0; i < 4; ++i) {
            int idx = tid + 256 * i;
            int row = idx >> 3, c8 = idx & 7;
            cp_async16(s + (uint32_t)row * (ASTR * 2) + (uint32_t)c8 * 16,
                       Ac + (size_t)row * Kdim + c8 * 8);
        }
        // B tile: 64 k-rows x 16 chunks = 1024 -> 4 per thread
        uint32_t sb = s + A_HALVES * 2;
        #pragma unroll
        for (int i = 0; i < 4; ++i) {
            int idx = tid + 256 * i;
            int k = idx >> 4, c8 = idx & 15;
            cp_async16(sb + (uint32_t)k * (BSTR * 2) + (uint32_t)c8 * 16,
                       Bc + (size_t)k * Ndim + c8 * 8);
        }
    };

    float acc[4][4][4];
    #pragma unroll
    for (int a = 0; a < 4; a++)
        #pragma unroll
        for (int b = 0; b < 4; b++)
            #pragma unroll
            for (int c = 0; c < 4; c++) acc[a][b][c] = 0.f;

    issue_loads(0); cp_commit();
    issue_loads(1); cp_commit();

    for (int kt = 0; kt < KT; ++kt) {
        cp_wait<1>();
        __syncthreads();
        if (kt + 2 < KT) issue_loads(kt + 2);
        cp_commit();   // exactly one group per iteration keeps wait<1> exact

        uint32_t s = smem_base + (uint32_t)(kt % STAGES) * (STAGE_HALVES * 2);
        uint32_t sb = s + A_HALVES * 2;

        #pragma unroll
        for (int ks = 0; ks < 4; ++ks) {     // 4 x k16 steps
            const int k0 = ks * 16;
            uint32_t af[4][4], bf[4][2];
            // A fragments: 4 ldmatrix.x4 over m64 x k16
            #pragma unroll
            for (int mt = 0; mt < 4; ++mt) {
                int r = wm * 64 + mt * 16 + lrow;
                uint32_t addr = s + (uint32_t)r * (ASTR * 2) + (uint32_t)(k0 + lcol8) * 2;
                ldsm_x4(af[mt][0], af[mt][1], af[mt][2], af[mt][3], addr);
            }
            // B fragments: 2 ldmatrix.x4.trans over k16 x n32
            #pragma unroll
            for (int np = 0; np < 2; ++np) {
                int krow = k0 + lrow;
                int c = wn * 32 + np * 16 + lcol8;
                uint32_t addr = sb + (uint32_t)krow * (BSTR * 2) + (uint32_t)c * 2;
                ldsm_x4_t(bf[np * 2][0], bf[np * 2][1], bf[np * 2 + 1][0], bf[np * 2 + 1][1], addr);
            }
            #pragma unroll
            for (int mt = 0; mt < 4; ++mt)
                #pragma unroll
                for (int nt = 0; nt < 4; ++nt) {
                    if (ACC16) {
                        // fp16-accumulate MMA with C=0; promote 16-term partial to fp32.
                        uint32_t d0, d1;
                        uint32_t z = 0;
                        asm volatile(
                            "mma.sync.aligned.m16n8k16.row.col.f16.f16.f16.f16 "
                            "{%0,%1}, {%2,%3,%4,%5}, {%6,%7}, {%8,%8};\n"
                            : "=r"(d0), "=r"(d1)
                            : "r"(af[mt][0]), "r"(af[mt][1]), "r"(af[mt][2]), "r"(af[mt][3]),
                              "r"(bf[nt][0]), "r"(bf[nt][1]), "r"(z));
                        float2 f0 = __half22float2(*(__half2*)&d0);
                        float2 f1 = __half22float2(*(__half2*)&d1);
                        acc[mt][nt][0] += f0.x; acc[mt][nt][1] += f0.y;
                        acc[mt][nt][2] += f1.x; acc[mt][nt][3] += f1.y;
                    } else {
                        asm volatile(
                            "mma.sync.aligned.m16n8k16.row.col.f32.f16.f16.f32 "
                            "{%0,%1,%2,%3}, {%4,%5,%6,%7}, {%8,%9}, {%0,%1,%2,%3};\n"
                            : "+f"(acc[mt][nt][0]), "+f"(acc[mt][nt][1]),
                              "+f"(acc[mt][nt][2]), "+f"(acc[mt][nt][3])
                            : "r"(af[mt][0]), "r"(af[mt][1]), "r"(af[mt][2]), "r"(af[mt][3]),
                              "r"(bf[nt][0]), "r"(bf[nt][1]));
                    }
                }
        }
    }

    // Epilogue. C fragment: c0:(grp,2q) c1:(grp,2q+1) c2:(grp+8,2q) c3:(grp+8,2q+1)
    if (GELU) {
        __half* D = (__half*)Dall + (size_t)e * Mdim * Ndim
                  + (size_t)blockIdx.y * BM * Ndim + blockIdx.x * BN;
        #pragma unroll
        for (int mt = 0; mt < 4; ++mt) {
            int r = wm * 64 + mt * 16 + grp;
            #pragma unroll
            for (int nt = 0; nt < 4; ++nt) {
                int c = wn * 32 + nt * 8 + 2 * qid;
                __half2 h0 = __float22half2_rn(make_float2(gelu_exact(acc[mt][nt][0]),
                                                           gelu_exact(acc[mt][nt][1])));
                __half2 h1 = __float22half2_rn(make_float2(gelu_exact(acc[mt][nt][2]),
                                                           gelu_exact(acc[mt][nt][3])));
                *(__half2*)(&D[(size_t)r * Ndim + c])       = h0;
                *(__half2*)(&D[(size_t)(r + 8) * Ndim + c]) = h1;
            }
        }
        // Tail: grid-stride fp32->fp16 convert (hides wo conversion under GEMM1; DRAM ~5% busy).
        if (cvt_n4) {
            size_t bid = (size_t)blockIdx.x
                       + (size_t)gridDim.x * ((size_t)blockIdx.y + (size_t)gridDim.y * blockIdx.z);
            size_t i = bid * blockDim.x + tid;
            size_t stride = (size_t)gridDim.x * gridDim.y * gridDim.z * blockDim.x;
            const float4* in4 = (const float4*)cvt_src;
            uint2* out4 = (uint2*)cvt_dst;
            for (; i < cvt_n4; i += stride) {
                float4 v = in4[i];
                __half2 lo = __float22half2_rn(make_float2(v.x, v.y));
                __half2 hi = __float22half2_rn(make_float2(v.z, v.w));
                uint2 o; o.x = *(uint32_t*)&lo; o.y = *(uint32_t*)&hi;
                out4[i] = o;
            }
        }
    } else {
        float* D = (float*)Dall + (size_t)e * Mdim * Ndim
                 + (size_t)blockIdx.y * BM * Ndim + blockIdx.x * BN;
        #pragma unroll
        for (int mt = 0; mt < 4; ++mt) {
            int r = wm * 64 + mt * 16 + grp;
            #pragma unroll
            for (int nt = 0; nt < 4; ++nt) {
                int c = wn * 32 + nt * 8 + 2 * qid;
                *(float2*)(&D[(size_t)r * Ndim + c]) =
                    make_float2(acc[mt][nt][0], acc[mt][nt][1]);
                *(float2*)(&D[(size_t)(r + 8) * Ndim + c]) =
                    make_float2(acc[mt][nt][2], acc[mt][nt][3]);
            }
        }
    }
}

extern "C" void kernel_launch(void* const* d_in, const int* in_sizes, int n_in,
                              void* d_out, int out_size) {
    const float* x  = (const float*)d_in[0];   // [8, 2048, 1024]
    const float* wi = (const float*)d_in[1];   // [8, 1024, 4096]  (= [K,N] per expert)
    const float* wo = (const float*)d_in[2];   // [8, 4096, 1024]  (= [K,N] per expert)
    float* out = (float*)d_out;                // [8, 2048, 1024] fp32

    __half *xh, *wih, *woh, *act;
    cudaGetSymbolAddress((void**)&xh,  g_xh);
    cudaGetSymbolAddress((void**)&wih, g_wih);
    cudaGetSymbolAddress((void**)&woh, g_woh);
    cudaGetSymbolAddress((void**)&act, g_act);

    cudaFuncSetAttribute(gemm_f16_w8<true, false>,
                         cudaFuncAttributeMaxDynamicSharedMemorySize, SMEM_BYTES);
    cudaFuncSetAttribute(gemm_f16_w8<false, true>,
                         cudaFuncAttributeMaxDynamicSharedMemorySize, SMEM_BYTES);

    const size_t nx  = (size_t)NUM_E * M_TOK * H_DIM;
    const size_t nwi = (size_t)NUM_E * H_DIM * I_DIM;
    const size_t nwo = (size_t)NUM_E * I_DIM * H_DIM;

    // Serial converts GEMM1 depends on:
    cvt_f32_f16<<<1216, 256>>>(x,  xh,  nx  / 4);
    cvt_f32_f16<<<1216, 256>>>(wi, wih, nwi / 4);

    // GEMM1: act = gelu(x @ wi), M=2048 N=4096 K=1024, fp32-acc, fp16 out, + hidden wo convert
    gemm_f16_w8<true, false><<<dim3(I_DIM / BN, M_TOK / BM, NUM_E), 256, SMEM_BYTES>>>(
        xh, wih, act, M_TOK, I_DIM, H_DIM, wo, woh, nwo / 4);

    // GEMM2: out = act @ wo, M=2048 N=1024 K=4096, fp16-acc probe (per-MMA promote), fp32 out
    gemm_f16_w8<false, true><<<dim3(H_DIM / BN, M_TOK / BM, NUM_E), 256, SMEM_BYTES>>>(
        act, woh, out, M_TOK, H_DIM, I_DIM, nullptr, nullptr, 0);
}

// round 17
// speedup vs baseline: 1.2203x; 1.2203x over previous
#include <cuda_runtime.h>
#include <cuda_fp16.h>
#include <cstdint>
#include <math.h>

// ---------------- problem constants ----------------
#define NUM_E 8
#define M_TOK 2048
#define H_DIM 1024
#define I_DIM 4096

// ---------------- fp16 scratch (no allocs allowed) ----------------
__device__ __half g_xh [(size_t)NUM_E * M_TOK * H_DIM];   //  32 MB
__device__ __half g_wih[(size_t)NUM_E * H_DIM * I_DIM];   //  64 MB
__device__ __half g_woh[(size_t)NUM_E * I_DIM * H_DIM];   //  64 MB
__device__ __half g_act[(size_t)NUM_E * M_TOK * I_DIM];   // 128 MB

// ---------------- tile config (round-13 proven shape) ----------------
#define BM 128
#define BN 128
#define BK 64
#define STAGES 3
#define ASTR 72             // halves; 144B rows -> ldsm rows hit banks 4r mod 32 (disjoint per phase)
#define BSTR 136            // halves; 272B rows -> banks 4k mod 32 (disjoint per phase)
#define A_HALVES (BM * ASTR)                 // 9216
#define B_HALVES (BK * BSTR)                 // 8704
#define STAGE_HALVES (A_HALVES + B_HALVES)   // 17920 halves = 35840 B
#define SMEM_BYTES (STAGES * STAGE_HALVES * 2)  // 107520 B/CTA -> 2 CTAs/SM

__device__ __forceinline__ void cp_async16(uint32_t smem, const void* gmem) {
    asm volatile("cp.async.cg.shared.global [%0], [%1], 16;\n" :: "r"(smem), "l"(gmem));
}
__device__ __forceinline__ void cp_commit() { asm volatile("cp.async.commit_group;\n" ::: "memory"); }
template <int N> __device__ __forceinline__ void cp_wait() {
    asm volatile("cp.async.wait_group %0;\n" :: "n"(N) : "memory");
}
__device__ __forceinline__ void ldsm_x4(uint32_t& r0, uint32_t& r1, uint32_t& r2, uint32_t& r3,
                                        uint32_t addr) {
    asm volatile("ldmatrix.sync.aligned.m8n8.x4.shared.b16 {%0,%1,%2,%3}, [%4];"
                 : "=r"(r0), "=r"(r1), "=r"(r2), "=r"(r3) : "r"(addr));
}
__device__ __forceinline__ void ldsm_x4_t(uint32_t& r0, uint32_t& r1, uint32_t& r2, uint32_t& r3,
                                          uint32_t addr) {
    asm volatile("ldmatrix.sync.aligned.m8n8.x4.trans.shared.b16 {%0,%1,%2,%3}, [%4];"
                 : "=r"(r0), "=r"(r1), "=r"(r2), "=r"(r3) : "r"(addr));
}
__device__ __forceinline__ float gelu_exact(float v) {
    return 0.5f * v * (1.0f + erff(v * 0.70710678118654752440f));
}

__device__ __forceinline__ void cvt_range(const float4* __restrict__ in4, uint2* __restrict__ out4,
                                          size_t n4, size_t start, size_t stride) {
    for (size_t i = start; i < n4; i += stride) {
        float4 v = in4[i];
        __half2 lo = __float22half2_rn(make_float2(v.x, v.y));
        __half2 hi = __float22half2_rn(make_float2(v.z, v.w));
        uint2 o; o.x = *(uint32_t*)&lo; o.y = *(uint32_t*)&hi;
        out4[i] = o;
    }
}

// ---------------- merged fp32->fp16 conversion: x and wi in one launch ----------------
__global__ void __launch_bounds__(256) cvt_two(const float* __restrict__ a, __half* __restrict__ ah,
                                               size_t na4,
                                               const float* __restrict__ b, __half* __restrict__ bh,
                                               size_t nb4) {
    size_t start = (size_t)blockIdx.x * blockDim.x + threadIdx.x;
    size_t stride = (size_t)gridDim.x * blockDim.x;
    cvt_range((const float4*)a, (uint2*)ah, na4, start, stride);
    cvt_range((const float4*)b, (uint2*)bh, nb4, start, stride);
}

// ---------------- fp16 GEMM: 256 threads, 8 warps (2x4), warp tile 64x32 ----------------
// A: [Mdim, Kdim] fp16 row-major per expert.  B: [Kdim, Ndim] fp16 row-major per expert.
// GELU=true: D fp16 + optional tail convert (hides wo). GELU=false: D fp32.
template <bool GELU>
__global__ void __launch_bounds__(256, 2) gemm_f16_w8(
    const __half* __restrict__ Aall, const __half* __restrict__ Ball, void* __restrict__ Dall,
    int Mdim, int Ndim, int Kdim,
    const float* __restrict__ cvt_src, __half* __restrict__ cvt_dst, size_t cvt_n4)
{
    extern __shared__ __half smem[];
    const uint32_t smem_base = (uint32_t)__cvta_generic_to_shared(smem);

    const int e = blockIdx.z;
    const __half* A = Aall + (size_t)e * Mdim * Kdim + (size_t)blockIdx.y * BM * Kdim;
    const __half* B = Ball + (size_t)e * Kdim * Ndim + (size_t)blockIdx.x * BN;

    const int tid = threadIdx.x;
    const int warp = tid >> 5;
    const int lane = tid & 31;
    const int wm = warp >> 2;      // 0..1 -> 64-row band
    const int wn = warp & 3;       // 0..3 -> 32-col band
    const int grp = lane >> 2;     // 0..7
    const int qid = lane & 3;      // 0..3
    const int lrow = lane & 15;
    const int lcol8 = (lane >> 4) * 8;

    const int KT = Kdim / BK;

    auto issue_loads = [&](int chunk) {
        uint32_t s = smem_base + (uint32_t)(chunk % STAGES) * (STAGE_HALVES * 2);
        const __half* Ac = A + chunk * BK;
        const __half* Bc = B + (size_t)chunk * BK * Ndim;
        // A tile: 128 rows x 8 chunks of 16B = 1024 -> 4 per thread
        #pragma unroll
        for (int i = 0; i < 4; ++i) {
            int idx = tid + 256 * i;
            int row = idx >> 3, c8 = idx & 7;
            cp_async16(s + (uint32_t)row * (ASTR * 2) + (uint32_t)c8 * 16,
                       Ac + (size_t)row * Kdim + c8 * 8);
        }
        // B tile: 64 k-rows x 16 chunks = 1024 -> 4 per thread
        uint32_t sb = s + A_HALVES * 2;
        #pragma unroll
        for (int i = 0; i < 4; ++i) {
            int idx = tid + 256 * i;
            int k = idx >> 4, c8 = idx & 15;
            cp_async16(sb + (uint32_t)k * (BSTR * 2) + (uint32_t)c8 * 16,
                       Bc + (size_t)k * Ndim + c8 * 8);
        }
    };

    float acc[4][4][4];
    #pragma unroll
    for (int a = 0; a < 4; a++)
        #pragma unroll
        for (int b = 0; b < 4; b++)
            #pragma unroll
            for (int c = 0; c < 4; c++) acc[a][b][c] = 0.f;

    issue_loads(0); cp_commit();
    issue_loads(1); cp_commit();

    for (int kt = 0; kt < KT; ++kt) {
        cp_wait<1>();
        __syncthreads();
        if (kt + 2 < KT) issue_loads(kt + 2);
        cp_commit();   // exactly one group per iteration keeps wait<1> exact

        uint32_t s = smem_base + (uint32_t)(kt % STAGES) * (STAGE_HALVES * 2);
        uint32_t sb = s + A_HALVES * 2;

        #pragma unroll
        for (int ks = 0; ks < 4; ++ks) {     // 4 x k16 steps
            const int k0 = ks * 16;
            uint32_t af[4][4], bf[4][2];
            // A fragments: 4 ldmatrix.x4 over m64 x k16
            #pragma unroll
            for (int mt = 0; mt < 4; ++mt) {
                int r = wm * 64 + mt * 16 + lrow;
                uint32_t addr = s + (uint32_t)r * (ASTR * 2) + (uint32_t)(k0 + lcol8) * 2;
                ldsm_x4(af[mt][0], af[mt][1], af[mt][2], af[mt][3], addr);
            }
            // B fragments: 2 ldmatrix.x4.trans over k16 x n32
            #pragma unroll
            for (int np = 0; np < 2; ++np) {
                int krow = k0 + lrow;
                int c = wn * 32 + np * 16 + lcol8;
                uint32_t addr = sb + (uint32_t)krow * (BSTR * 2) + (uint32_t)c * 2;
                ldsm_x4_t(bf[np * 2][0], bf[np * 2][1], bf[np * 2 + 1][0], bf[np * 2 + 1][1], addr);
            }
            #pragma unroll
            for (int mt = 0; mt < 4; ++mt)
                #pragma unroll
                for (int nt = 0; nt < 4; ++nt) {
                    asm volatile(
                        "mma.sync.aligned.m16n8k16.row.col.f32.f16.f16.f32 "
                        "{%0,%1,%2,%3}, {%4,%5,%6,%7}, {%8,%9}, {%0,%1,%2,%3};\n"
                        : "+f"(acc[mt][nt][0]), "+f"(acc[mt][nt][1]),
                          "+f"(acc[mt][nt][2]), "+f"(acc[mt][nt][3])
                        : "r"(af[mt][0]), "r"(af[mt][1]), "r"(af[mt][2]), "r"(af[mt][3]),
                          "r"(bf[nt][0]), "r"(bf[nt][1]));
                }
        }
    }

    // Epilogue. C fragment: c0:(grp,2q) c1:(grp,2q+1) c2:(grp+8,2q) c3:(grp+8,2q+1)
    if (GELU) {
        __half* D = (__half*)Dall + (size_t)e * Mdim * Ndim
                  + (size_t)blockIdx.y * BM * Ndim + blockIdx.x * BN;
        #pragma unroll
        for (int mt = 0; mt < 4; ++mt) {
            int r = wm * 64 + mt * 16 + grp;
            #pragma unroll
            for (int nt = 0; nt < 4; ++nt) {
                int c = wn * 32 + nt * 8 + 2 * qid;
                __half2 h0 = __float22half2_rn(make_float2(gelu_exact(acc[mt][nt][0]),
                                                           gelu_exact(acc[mt][nt][1])));
                __half2 h1 = __float22half2_rn(make_float2(gelu_exact(acc[mt][nt][2]),
                                                           gelu_exact(acc[mt][nt][3])));
                *(__half2*)(&D[(size_t)r * Ndim + c])       = h0;
                *(__half2*)(&D[(size_t)(r + 8) * Ndim + c]) = h1;
            }
        }
        // Tail: grid-stride fp32->fp16 convert (hides wo conversion under GEMM1; DRAM ~5% busy).
        if (cvt_n4) {
            size_t bid = (size_t)blockIdx.x
                       + (size_t)gridDim.x * ((size_t)blockIdx.y + (size_t)gridDim.y * blockIdx.z);
            size_t i = bid * blockDim.x + tid;
            size_t stride = (size_t)gridDim.x * gridDim.y * gridDim.z * blockDim.x;
            cvt_range((const float4*)cvt_src, (uint2*)cvt_dst, cvt_n4, i, stride);
        }
    } else {
        float* D = (float*)Dall + (size_t)e * Mdim * Ndim
                 + (size_t)blockIdx.y * BM * Ndim + blockIdx.x * BN;
        #pragma unroll
        for (int mt = 0; mt < 4; ++mt) {
            int r = wm * 64 + mt * 16 + grp;
            #pragma unroll
            for (int nt = 0; nt < 4; ++nt) {
                int c = wn * 32 + nt * 8 + 2 * qid;
                *(float2*)(&D[(size_t)r * Ndim + c]) =
                    make_float2(acc[mt][nt][0], acc[mt][nt][1]);
                *(float2*)(&D[(size_t)(r + 8) * Ndim + c]) =
                    make_float2(acc[mt][nt][2], acc[mt][nt][3]);
            }
        }
    }
}

extern "C" void kernel_launch(void* const* d_in, const int* in_sizes, int n_in,
                              void* d_out, int out_size) {
    const float* x  = (const float*)d_in[0];   // [8, 2048, 1024]
    const float* wi = (const float*)d_in[1];   // [8, 1024, 4096]  (= [K,N] per expert)
    const float* wo = (const float*)d_in[2];   // [8, 4096, 1024]  (= [K,N] per expert)
    float* out = (float*)d_out;                // [8, 2048, 1024] fp32

    __half *xh, *wih, *woh, *act;
    cudaGetSymbolAddress((void**)&xh,  g_xh);
    cudaGetSymbolAddress((void**)&wih, g_wih);
    cudaGetSymbolAddress((void**)&woh, g_woh);
    cudaGetSymbolAddress((void**)&act, g_act);

    cudaFuncSetAttribute(gemm_f16_w8<true>,
                         cudaFuncAttributeMaxDynamicSharedMemorySize, SMEM_BYTES);
    cudaFuncSetAttribute(gemm_f16_w8<false>,
                         cudaFuncAttributeMaxDynamicSharedMemorySize, SMEM_BYTES);

    const size_t nx  = (size_t)NUM_E * M_TOK * H_DIM;
    const size_t nwi = (size_t)NUM_E * H_DIM * I_DIM;
    const size_t nwo = (size_t)NUM_E * I_DIM * H_DIM;

    // Serial converts GEMM1 depends on (x + wi, one launch):
    cvt_two<<<2432, 256>>>(x, xh, nx / 4, wi, wih, nwi / 4);

    // GEMM1: act = gelu(x @ wi), M=2048 N=4096 K=1024, fp32-acc, fp16 out, + hidden wo convert
    gemm_f16_w8<true><<<dim3(I_DIM / BN, M_TOK / BM, NUM_E), 256, SMEM_BYTES>>>(
        xh, wih, act, M_TOK, I_DIM, H_DIM, wo, woh, nwo / 4);

    // GEMM2: out = act @ wo, M=2048 N=1024 K=4096, fp32-acc, fp32 out
    gemm_f16_w8<false><<<dim3(H_DIM / BN, M_TOK / BM, NUM_E), 256, SMEM_BYTES>>>(
        act, woh, out, M_TOK, H_DIM, I_DIM, nullptr, nullptr, 0);
}